// round 10
// baseline (speedup 1.0000x reference)
#include <cuda_runtime.h>
#include <cuda_bf16.h>

#define IMG_W 416
#define IMG_H 416
#define NCH   3
#define TPB   256
#define QROW  104                    // float4 quads per row
#define CS    (IMG_W * IMG_H)        // 173056
#define BLKX  169                    // 169*256 = 416*104 threads per sample

__global__ void __launch_bounds__(TPB)
sample_kernel(const float* __restrict__ img,
              const float* __restrict__ bb,
              const float* __restrict__ angle,
              const int*   __restrict__ pos_ptr,
              float* __restrict__ out) {
    const int n = blockIdx.y;
    const int i = blockIdx.x * TPB + threadIdx.x;   // 0 .. 43263
    const int y  = i / QROW;
    const int xq = i - y * QROW;

    // ---- theta: lane 0 computes with fast intrinsics, warp broadcasts ----
    float t00, t01, t02, t10, t11, t12;
    if ((threadIdx.x & 31) == 0) {
        float patch_ori = 300.0f;
        if (pos_ptr) {
            int pi = pos_ptr[0];
            patch_ori = (pi > 0 && pi < 1000000) ? (float)pi : __int_as_float(pi);
        }
        float x1 = bb[n * 6 + 0];
        float y1 = bb[n * 6 + 1];
        float x2 = bb[n * 6 + 2];
        float y2 = bb[n * 6 + 3];

        float bwv = (x2 - x1) * (float)IMG_W;
        float bhv = (y2 - y1) * (float)IMG_H;
        float cx  = (x1 + x2) * 0.5f;
        float cy  = (y1 + y2) * 0.5f - (y2 - y1) * 0.1f;
        float tx  = (0.5f - cx) * 2.0f;
        float ty  = (0.5f - cy) * 2.0f;
        float target = 0.2f * sqrtf(bwv * bwv + bhv * bhv);
        // fast reciprocal of scale: rs = patch_ori / target  (benign ranges)
        float rs = __fdividef(patch_ori, target);

        float s, c;
        __sincosf(angle[n], &s, &c);     // |angle| <= 0.35 rad

        t00 = c * rs;
        t01 = s * rs;
        t02 = (tx * c + ty * s) * rs;
        t10 = -s * rs;
        t11 = c * rs;
        t12 = (ty * c - tx * s) * rs;
    }
    t00 = __shfl_sync(0xffffffffu, t00, 0);
    t01 = __shfl_sync(0xffffffffu, t01, 0);
    t02 = __shfl_sync(0xffffffffu, t02, 0);
    t10 = __shfl_sync(0xffffffffu, t10, 0);
    t11 = __shfl_sync(0xffffffffu, t11, 0);
    t12 = __shfl_sync(0xffffffffu, t12, 0);

    // approx pixel-map constants (classification only; 0.5+ px margin below)
    const float Kx = fmaf(-207.5f, t00 + t01, fmaf(208.0f, t02, 207.5f));
    const float Ky = fmaf(-207.5f, t10 + t11, fmaf(208.0f, t12, 207.5f));

    // ---- quad classification via endpoint coords ----
    const float yf = (float)y;
    const float Rx = fmaf(t01, yf, Kx);
    const float Ry = fmaf(t11, yf, Ky);
    const int xbase = xq * 4;

    const float ix0 = fmaf(t00, (float)xbase, Rx);
    const float iy0 = fmaf(t10, (float)xbase, Ry);
    const float ix3 = fmaf(t00, (float)(xbase + 3), Rx);
    const float iy3 = fmaf(t10, (float)(xbase + 3), Ry);

    const bool any = (fmaxf(ix0, ix3) > -1.5f) && (fminf(ix0, ix3) < 416.5f) &&
                     (fmaxf(iy0, iy3) > -1.5f) && (fminf(iy0, iy3) < 416.5f);

    const int obase = (n * NCH * IMG_H + y) * IMG_W + xbase;

    if (!any) {
        // Fast path (~99.5%): pure zero writes, no reads.
        const float4 z = make_float4(0.f, 0.f, 0.f, 0.f);
        *(float4*)(out + obase)          = z;
        *(float4*)(out + obase + CS)     = z;
        *(float4*)(out + obase + 2 * CS) = z;
        return;
    }

    // ---- slow path: exact validated arithmetic ----
    const float ysv = __fdiv_rn(2.0f * yf + 1.0f, (float)IMG_W) - 1.0f;
    const float Cx = fmaf(208.0f, fmaf(t01, ysv, t02), fmaf(-207.5f, t00, 207.5f));
    const float Cy = fmaf(208.0f, fmaf(t11, ysv, t12), fmaf(-207.5f, t10, 207.5f));

    const float* base = img + (size_t)n * NCH * CS;
    float acc0[4], acc1[4], acc2[4];
#pragma unroll
    for (int p = 0; p < 4; p++) {
        const float xf = (float)(xbase + p);
        const float ix = fmaf(t00, xf, Cx);
        const float iy = fmaf(t10, xf, Cy);

        float fx0 = floorf(ix), fy0 = floorf(iy);
        int   x0  = (int)fx0,   y0  = (int)fy0;
        float wx1 = ix - fx0,   wy1 = iy - fy0;
        float wx0 = 1.0f - wx1, wy0 = 1.0f - wy1;

        bool vx0 = (x0 >= 0)  && (x0 < IMG_W);
        bool vx1 = (x0 >= -1) && (x0 < IMG_W - 1);
        bool vy0 = (y0 >= 0)  && (y0 < IMG_H);
        bool vy1 = (y0 >= -1) && (y0 < IMG_H - 1);

        float w00 = (vx0 && vy0) ? wx0 * wy0 : 0.0f;
        float w10 = (vx1 && vy0) ? wx1 * wy0 : 0.0f;
        float w01 = (vx0 && vy1) ? wx0 * wy1 : 0.0f;
        float w11 = (vx1 && vy1) ? wx1 * wy1 : 0.0f;

        float a0 = 0.f, a1 = 0.f, a2 = 0.f;
        int i00 = y0 * IMG_W + x0;
        if (w00 != 0.0f) {
            a0 = fmaf(w00, __ldg(base + i00), a0);
            a1 = fmaf(w00, __ldg(base + CS + i00), a1);
            a2 = fmaf(w00, __ldg(base + 2 * CS + i00), a2);
        }
        if (w10 != 0.0f) {
            int idx2 = i00 + 1;
            a0 = fmaf(w10, __ldg(base + idx2), a0);
            a1 = fmaf(w10, __ldg(base + CS + idx2), a1);
            a2 = fmaf(w10, __ldg(base + 2 * CS + idx2), a2);
        }
        if (w01 != 0.0f) {
            int idx2 = i00 + IMG_W;
            a0 = fmaf(w01, __ldg(base + idx2), a0);
            a1 = fmaf(w01, __ldg(base + CS + idx2), a1);
            a2 = fmaf(w01, __ldg(base + 2 * CS + idx2), a2);
        }
        if (w11 != 0.0f) {
            int idx2 = i00 + IMG_W + 1;
            a0 = fmaf(w11, __ldg(base + idx2), a0);
            a1 = fmaf(w11, __ldg(base + CS + idx2), a1);
            a2 = fmaf(w11, __ldg(base + 2 * CS + idx2), a2);
        }
        acc0[p] = a0;
        acc1[p] = a1;
        acc2[p] = a2;
    }

    *(float4*)(out + obase)          = make_float4(acc0[0], acc0[1], acc0[2], acc0[3]);
    *(float4*)(out + obase + CS)     = make_float4(acc1[0], acc1[1], acc1[2], acc1[3]);
    *(float4*)(out + obase + 2 * CS) = make_float4(acc2[0], acc2[1], acc2[2], acc2[3]);
}

extern "C" void kernel_launch(void* const* d_in, const int* in_sizes, int n_in,
                              void* d_out, int out_size) {
    const float* img = (const float*)d_in[0];   // adv_patch_batch (B,L,C,H,W) f32
    const float* bb  = (const float*)d_in[1];   // bboxes_batch (B,L,6) f32
    const float* ang = (const float*)d_in[2];   // angle (B*L,) f32
    const int*   pos = (n_in > 3) ? (const int*)d_in[3] : nullptr;

    int N = in_sizes[2];                        // B*L = 128

    dim3 grid(BLKX, N);
    sample_kernel<<<grid, TPB>>>(img, bb, ang, pos, (float*)d_out);
}

// round 13
// speedup vs baseline: 1.1208x; 1.1208x over previous
#include <cuda_runtime.h>
#include <cuda_bf16.h>

#define IMG_W 416
#define IMG_H 416
#define NCH   3
#define TPB   256
#define QROW  104                    // float4 quads per row
#define CS    (IMG_W * IMG_H)        // 173056
#define PER_N (IMG_H * QROW)         // 43264 threads per sample (multiple of 32)

__global__ void __launch_bounds__(TPB)
sample_kernel(const float* __restrict__ img,
              const float* __restrict__ bb,
              const float* __restrict__ angle,
              const int*   __restrict__ pos_ptr,
              float* __restrict__ out, int total) {
    const int tid = blockIdx.x * TPB + threadIdx.x;
    if (tid >= total) return;               // total is a multiple of 32

    const int xq = tid % QROW;
    const int t2 = tid / QROW;
    const int y  = t2 % IMG_H;
    const int n  = t2 / IMG_H;              // same n for all lanes of a warp

    // ---- theta: lane 0 computes (divergent branch, fast intrinsics), ----
    // ---- warp broadcasts. n is thread-derived so the branch stays real. ----
    float t00, t01, t02, t10, t11, t12, Kx, Ky;
    if ((threadIdx.x & 31) == 0) {
        float patch_ori = 300.0f;
        if (pos_ptr) {
            int pi = pos_ptr[0];
            patch_ori = (pi > 0 && pi < 1000000) ? (float)pi : __int_as_float(pi);
        }
        float x1 = bb[n * 6 + 0];
        float y1 = bb[n * 6 + 1];
        float x2 = bb[n * 6 + 2];
        float y2 = bb[n * 6 + 3];

        float bwv = (x2 - x1) * (float)IMG_W;
        float bhv = (y2 - y1) * (float)IMG_H;
        float cx  = (x1 + x2) * 0.5f;
        float cy  = (y1 + y2) * 0.5f - (y2 - y1) * 0.1f;
        float tx  = (0.5f - cx) * 2.0f;
        float ty  = (0.5f - cy) * 2.0f;
        float target = 0.2f * sqrtf(bwv * bwv + bhv * bhv);
        // rs = 1/scale = patch_ori / target  (benign ranges; fast divide)
        float rs = __fdividef(patch_ori, target);

        float s, c;
        __sincosf(angle[n], &s, &c);        // |angle| <= 0.35 rad

        t00 = c * rs;
        t01 = s * rs;
        t02 = (tx * c + ty * s) * rs;
        t10 = -s * rs;
        t11 = c * rs;
        t12 = (ty * c - tx * s) * rs;

        // approx pixel-map constants (classification only, margin below)
        Kx = 207.5f - 207.5f * t00 - 207.5f * t01 + 208.0f * t02;
        Ky = 207.5f - 207.5f * t10 - 207.5f * t11 + 208.0f * t12;
    }
    t00 = __shfl_sync(0xffffffffu, t00, 0);
    t01 = __shfl_sync(0xffffffffu, t01, 0);
    t02 = __shfl_sync(0xffffffffu, t02, 0);
    t10 = __shfl_sync(0xffffffffu, t10, 0);
    t11 = __shfl_sync(0xffffffffu, t11, 0);
    t12 = __shfl_sync(0xffffffffu, t12, 0);
    Kx  = __shfl_sync(0xffffffffu, Kx, 0);
    Ky  = __shfl_sync(0xffffffffu, Ky, 0);

    // ---- quad classification (approx coords + generous margin) ----
    const float yf = (float)y;
    const float Rx = fmaf(t01, yf, Kx);
    const float Ry = fmaf(t11, yf, Ky);
    const int xbase = xq * 4;

    const float ix0 = fmaf(t00, (float)xbase, Rx);
    const float iy0 = fmaf(t10, (float)xbase, Ry);
    const float ix3 = fmaf(t00, (float)(xbase + 3), Rx);
    const float iy3 = fmaf(t10, (float)(xbase + 3), Ry);

    const bool any = (fmaxf(ix0, ix3) > -1.5f) && (fminf(ix0, ix3) < 416.5f) &&
                     (fmaxf(iy0, iy3) > -1.5f) && (fminf(iy0, iy3) < 416.5f);

    const int obase = (n * NCH * IMG_H + y) * IMG_W + xbase;

    if (!any) {
        // Fast path (~99.5%): pure zero writes, no reads.
        const float4 z = make_float4(0.f, 0.f, 0.f, 0.f);
        *(float4*)(out + obase)          = z;
        *(float4*)(out + obase + CS)     = z;
        *(float4*)(out + obase + 2 * CS) = z;
        return;
    }

    // ---- slow path: exact validated arithmetic ----
    const float ysv = __fdiv_rn(2.0f * yf + 1.0f, (float)IMG_W) - 1.0f;
    const float Cx = fmaf(208.0f, fmaf(t01, ysv, t02), fmaf(-207.5f, t00, 207.5f));
    const float Cy = fmaf(208.0f, fmaf(t11, ysv, t12), fmaf(-207.5f, t10, 207.5f));

    const float* base = img + (size_t)n * NCH * CS;
    float acc0[4], acc1[4], acc2[4];
#pragma unroll
    for (int p = 0; p < 4; p++) {
        const float xf = (float)(xbase + p);
        const float ix = fmaf(t00, xf, Cx);
        const float iy = fmaf(t10, xf, Cy);

        float fx0 = floorf(ix), fy0 = floorf(iy);
        int   x0  = (int)fx0,   y0  = (int)fy0;
        float wx1 = ix - fx0,   wy1 = iy - fy0;
        float wx0 = 1.0f - wx1, wy0 = 1.0f - wy1;

        bool vx0 = (x0 >= 0)  && (x0 < IMG_W);
        bool vx1 = (x0 >= -1) && (x0 < IMG_W - 1);
        bool vy0 = (y0 >= 0)  && (y0 < IMG_H);
        bool vy1 = (y0 >= -1) && (y0 < IMG_H - 1);

        float w00 = (vx0 && vy0) ? wx0 * wy0 : 0.0f;
        float w10 = (vx1 && vy0) ? wx1 * wy0 : 0.0f;
        float w01 = (vx0 && vy1) ? wx0 * wy1 : 0.0f;
        float w11 = (vx1 && vy1) ? wx1 * wy1 : 0.0f;

        float a0 = 0.f, a1 = 0.f, a2 = 0.f;
        int i00 = y0 * IMG_W + x0;
        if (w00 != 0.0f) {
            a0 = fmaf(w00, __ldg(base + i00), a0);
            a1 = fmaf(w00, __ldg(base + CS + i00), a1);
            a2 = fmaf(w00, __ldg(base + 2 * CS + i00), a2);
        }
        if (w10 != 0.0f) {
            int i = i00 + 1;
            a0 = fmaf(w10, __ldg(base + i), a0);
            a1 = fmaf(w10, __ldg(base + CS + i), a1);
            a2 = fmaf(w10, __ldg(base + 2 * CS + i), a2);
        }
        if (w01 != 0.0f) {
            int i = i00 + IMG_W;
            a0 = fmaf(w01, __ldg(base + i), a0);
            a1 = fmaf(w01, __ldg(base + CS + i), a1);
            a2 = fmaf(w01, __ldg(base + 2 * CS + i), a2);
        }
        if (w11 != 0.0f) {
            int i = i00 + IMG_W + 1;
            a0 = fmaf(w11, __ldg(base + i), a0);
            a1 = fmaf(w11, __ldg(base + CS + i), a1);
            a2 = fmaf(w11, __ldg(base + 2 * CS + i), a2);
        }
        acc0[p] = a0;
        acc1[p] = a1;
        acc2[p] = a2;
    }

    *(float4*)(out + obase)          = make_float4(acc0[0], acc0[1], acc0[2], acc0[3]);
    *(float4*)(out + obase + CS)     = make_float4(acc1[0], acc1[1], acc1[2], acc1[3]);
    *(float4*)(out + obase + 2 * CS) = make_float4(acc2[0], acc2[1], acc2[2], acc2[3]);
}

extern "C" void kernel_launch(void* const* d_in, const int* in_sizes, int n_in,
                              void* d_out, int out_size) {
    const float* img = (const float*)d_in[0];   // adv_patch_batch (B,L,C,H,W) f32
    const float* bb  = (const float*)d_in[1];   // bboxes_batch (B,L,6) f32
    const float* ang = (const float*)d_in[2];   // angle (B*L,) f32
    const int*   pos = (n_in > 3) ? (const int*)d_in[3] : nullptr;

    int N = in_sizes[2];                        // B*L = 128
    int total = N * PER_N;

    sample_kernel<<<(total + TPB - 1) / TPB, TPB>>>(img, bb, ang, pos,
                                                    (float*)d_out, total);
}